// round 13
// baseline (speedup 1.0000x reference)
#include <cuda_runtime.h>
#include <cuda_fp16.h>
#include <math.h>
#include <stdint.h>

#define N_ 64
#define C_ 512
#define S_ 1024
#define K_ 64

// ---- scratch (device globals; allocation-free) ------------------------------
__device__ __half g_wh[K_ * C_];          // w as fp16
__device__ __half g_ah[N_ * K_ * S_];     // a' = softmax*invnorm, fp16
__device__ float g_asum[N_ * K_];
__device__ float g_vlad[N_ * K_ * C_];

// ---- helpers ----------------------------------------------------------------
__device__ __forceinline__ uint32_t smem_u32(const void* p) {
    return (uint32_t)__cvta_generic_to_shared((void*)p);
}
__device__ __forceinline__ void sts64(uint32_t addr, uint32_t v0, uint32_t v1) {
    asm volatile("st.shared.v2.b32 [%0], {%1, %2};" :: "r"(addr), "r"(v0), "r"(v1));
}
__device__ __forceinline__ void sts128(uint32_t addr, uint32_t v0, uint32_t v1,
                                       uint32_t v2, uint32_t v3) {
    asm volatile("st.shared.v4.b32 [%0], {%1, %2, %3, %4};"
                 :: "r"(addr), "r"(v0), "r"(v1), "r"(v2), "r"(v3));
}
__device__ __forceinline__ void cpa16(uint32_t dst, const void* src) {
    asm volatile("cp.async.cg.shared.global [%0], [%1], 16;" :: "r"(dst), "l"(src));
}
#define CP_COMMIT() asm volatile("cp.async.commit_group;" ::: "memory")
template <int N>
__device__ __forceinline__ void cp_wait() {
    asm volatile("cp.async.wait_group %0;" :: "n"(N) : "memory");
}
__device__ __forceinline__ void ldmx4(uint32_t r[4], uint32_t addr) {
    asm volatile("ldmatrix.sync.aligned.m8n8.x4.shared.b16 {%0,%1,%2,%3}, [%4];"
                 : "=r"(r[0]), "=r"(r[1]), "=r"(r[2]), "=r"(r[3]) : "r"(addr));
}
__device__ __forceinline__ void mma16816(float d[4], const uint32_t a[4],
                                         const uint32_t b[2]) {
    asm volatile(
        "mma.sync.aligned.m16n8k16.row.col.f32.f16.f16.f32 "
        "{%0,%1,%2,%3}, {%4,%5,%6,%7}, {%8,%9}, {%0,%1,%2,%3};"
        : "+f"(d[0]), "+f"(d[1]), "+f"(d[2]), "+f"(d[3])
        : "r"(a[0]), "r"(a[1]), "r"(a[2]), "r"(a[3]), "r"(b[0]), "r"(b[1]));
}
// pack two fp32 -> fp16x2 (lo = f0, hi = f1)
__device__ __forceinline__ uint32_t cvt2h(float f0, float f1) {
    uint32_t r;
    asm("cvt.rn.f16x2.f32 %0, %1, %2;" : "=r"(r) : "f"(f1), "f"(f0));
    return r;
}

// smem rows 144B padded (64 fp16 + pad)
#define RS 144
#define LS_STRIDE 66
// g1: A double-buffered (128 rows), B double-buffered (64 rows)
#define OA(b) ((b) * 18432)
#define OB(b) (36864 + (b) * 9216)
#define G1_SSQ 53248
#define SMEM_G1 55296
// g2: A double-buffered (64 rows), B double-buffered (64 rows)
#define QA(b) ((b) * 9216)
#define QB(b) (18432 + (b) * 9216)
#define SMEM_G2 36864

extern __shared__ char dsm[];

// ---------------------------------------------------------------------------
// k0: w -> fp16; zero asum.
// ---------------------------------------------------------------------------
__global__ void k0_prep(const float* __restrict__ w) {
    int i = blockIdx.x * 256 + threadIdx.x;
    g_wh[i] = __float2half(w[i]);
    if (i < N_ * K_) g_asum[i] = 0.f;
}

// ---------------------------------------------------------------------------
// B tile stage via cp.async: 64 rows x 64 fp16 from [r*ld + coff]. 4 cp/thread.
// ---------------------------------------------------------------------------
__device__ __forceinline__ void stageB(uint32_t Bd,
                                       const __half* __restrict__ src,
                                       int ld, int coff, int t) {
    int r0 = t >> 3;
    int cc = (t & 7) * 8;
#pragma unroll
    for (int it = 0; it < 4; ++it) {
        int r = it * 16 + r0;
        cpa16(Bd + r * RS + cc * 2, src + (size_t)r * ld + coff + cc);
    }
}

// one ks-slice, 128-row A (two m-tiles per warp)  [g1]
__device__ __forceinline__ void mma_ks(int ks, uint32_t A, uint32_t B,
                                       float acc[2][8][4], int w, int lane) {
    int arow = lane & 15;
    int asel = (lane >> 4) * 16;
    int brow = (lane & 7) + ((lane >> 4) << 3);
    int bsel = ((lane >> 3) & 1) * 16;
    int kb = ks * 32;
    uint32_t a[2][4];
#pragma unroll
    for (int mt = 0; mt < 2; ++mt)
        ldmx4(a[mt], A + (w * 32 + mt * 16 + arow) * RS + kb + asel);
    uint32_t b[8][2];
#pragma unroll
    for (int p = 0; p < 4; ++p) {
        uint32_t r[4];
        ldmx4(r, B + (p * 16 + brow) * RS + kb + bsel);
        b[2 * p][0] = r[0]; b[2 * p][1] = r[1];
        b[2 * p + 1][0] = r[2]; b[2 * p + 1][1] = r[3];
    }
#pragma unroll
    for (int mt = 0; mt < 2; ++mt)
#pragma unroll
        for (int nt = 0; nt < 8; ++nt)
            mma16816(acc[mt][nt], a[mt], b[nt]);
}

// one ks-slice, 64-row A (one m-tile per warp)  [g2]
__device__ __forceinline__ void mma_ks1(int ks, uint32_t A, uint32_t B,
                                        float acc[8][4], int w, int lane) {
    int arow = lane & 15;
    int asel = (lane >> 4) * 16;
    int brow = (lane & 7) + ((lane >> 4) << 3);
    int bsel = ((lane >> 3) & 1) * 16;
    int kb = ks * 32;
    uint32_t a[4];
    ldmx4(a, A + (w * 16 + arow) * RS + kb + asel);
#pragma unroll
    for (int p = 0; p < 4; ++p) {
        uint32_t r[4];
        ldmx4(r, B + (p * 16 + brow) * RS + kb + bsel);
        uint32_t b0[2] = { r[0], r[1] };
        uint32_t b1[2] = { r[2], r[3] };
        mma16816(acc[2 * p],     a, b0);
        mma16816(acc[2 * p + 1], a, b1);
    }
}

__device__ __forceinline__ void store_frags(float* Ls, float acc[2][8][4],
                                            int w, int lane) {
#pragma unroll
    for (int mt = 0; mt < 2; ++mt)
#pragma unroll
        for (int nt = 0; nt < 8; ++nt) {
            int r0 = w * 32 + mt * 16 + (lane >> 2);
            int c = nt * 8 + (lane & 3) * 2;
            Ls[r0 * LS_STRIDE + c]           = acc[mt][nt][0];
            Ls[r0 * LS_STRIDE + c + 1]       = acc[mt][nt][1];
            Ls[(r0 + 8) * LS_STRIDE + c]     = acc[mt][nt][2];
            Ls[(r0 + 8) * LS_STRIDE + c + 1] = acc[mt][nt][3];
        }
}

// ---------------------------------------------------------------------------
// g1: logits D[s=128,k=64] over C (8 chunks of 64). Unchanged from R11.
// ---------------------------------------------------------------------------
__global__ void __launch_bounds__(128) g1_logits(const float* __restrict__ x) {
    uint32_t sb = smem_u32(dsm);
    int t = threadIdx.x, w = t >> 5, lane = t & 31;
    int sl = t & 63, hi = t >> 6;
    int sp = 2 * sl;
    int cb = hi * 32;
    int n = blockIdx.y, s0 = blockIdx.x * 128;
    const float* xn = x + (size_t)n * C_ * S_ + s0;

    float acc[2][8][4];
#pragma unroll
    for (int i = 0; i < 2; ++i)
#pragma unroll
        for (int j = 0; j < 8; ++j)
#pragma unroll
            for (int q = 0; q < 4; ++q) acc[i][j][q] = 0.f;
    float sq0 = 0.f, sq1 = 0.f;
    float2 xr[32];

#define G1_LOADX(cc0)                                                         \
    _Pragma("unroll")                                                         \
    for (int j = 0; j < 32; ++j)                                              \
        xr[j] = *(const float2*)&xn[(size_t)((cc0) + cb + j) * S_ + sp];

#define G1_CVTG(dst, g) {                                                     \
        uint32_t u0[4], u1[4];                                                \
        _Pragma("unroll")                                                     \
        for (int q = 0; q < 4; ++q) {                                         \
            int cp = (g) * 4 + q;                                             \
            float2 va = xr[2 * cp], vb = xr[2 * cp + 1];                      \
            sq0 += va.x * va.x + vb.x * vb.x;                                 \
            sq1 += va.y * va.y + vb.y * vb.y;                                 \
            u0[q] = cvt2h(va.x, vb.x);                                        \
            u1[q] = cvt2h(va.y, vb.y);                                        \
        }                                                                     \
        sts128((dst) + sp * RS + (cb + (g) * 8) * 2,                          \
               u0[0], u0[1], u0[2], u0[3]);                                   \
        sts128((dst) + (sp + 1) * RS + (cb + (g) * 8) * 2,                    \
               u1[0], u1[1], u1[2], u1[3]); }

    G1_LOADX(0);
    stageB(sb + OB(0), g_wh, C_, 0, t);
    CP_COMMIT();
#pragma unroll
    for (int g = 0; g < 4; ++g) G1_CVTG(sb + OA(0), g);
    G1_LOADX(64);
    stageB(sb + OB(1), g_wh, C_, 64, t);
    CP_COMMIT();
    cp_wait<1>();
    __syncthreads();

    for (int ch = 0; ch < 8; ++ch) {
        int cur = ch & 1, nxt = (ch + 1) & 1;
        bool has_cvt = (ch + 1 < 8);
#pragma unroll
        for (int ks = 0; ks < 4; ++ks) {
            mma_ks(ks, sb + OA(cur), sb + OB(cur), acc, w, lane);
            if (has_cvt) G1_CVTG(sb + OA(nxt), ks);
        }
        if (ch + 2 < 8) { G1_LOADX((ch + 2) * 64); }
        __syncthreads();
        if (ch + 2 < 8) {
            stageB(sb + OB(cur), g_wh, C_, (ch + 2) * 64, t);
            CP_COMMIT();
            cp_wait<1>();
        } else if (ch + 1 < 8) {
            cp_wait<0>();
        }
        if (ch + 1 < 8) __syncthreads();
    }

    __syncthreads();

    float* Ls = (float*)dsm;
    float* ssq = (float*)(dsm + G1_SSQ);
    ssq[hi * 128 + sp]     = sq0;
    ssq[hi * 128 + sp + 1] = sq1;
    store_frags(Ls, acc, w, lane);
    __syncthreads();

    float sumsq = ssq[t] + ssq[128 + t];
    float inv = 1.f / fmaxf(sqrtf(sumsq), 1e-12f);
    float m = -1e30f;
#pragma unroll
    for (int k = 0; k < K_; ++k) m = fmaxf(m, Ls[t * LS_STRIDE + k] * inv);
    float sum = 0.f;
#pragma unroll
    for (int k = 0; k < K_; ++k) {
        float e = expf(Ls[t * LS_STRIDE + k] * inv - m);
        Ls[t * LS_STRIDE + k] = e;
        sum += e;
    }
    float rs = 1.f / sum;
#pragma unroll
    for (int k = 0; k < K_; ++k) {
        float a = Ls[t * LS_STRIDE + k] * rs;
        Ls[t * LS_STRIDE + k] = a;
        g_ah[(((size_t)n * K_ + k) << 10) + s0 + t] = __float2half(a * inv);
    }
    __syncthreads();
    if (t < K_) {
        float s = 0.f;
#pragma unroll
        for (int si = 0; si < 128; ++si) s += Ls[si * LS_STRIDE + t];
        atomicAdd(&g_asum[n * K_ + t], s);
    }
}

// ---------------------------------------------------------------------------
// g2: vlad D[c=64,k=64] over S (16 chunks of 64). c-tile 64 -> 512 blocks,
// warp owns 16 c-rows. Same mma fragment math (single m-tile variant).
// ---------------------------------------------------------------------------
__global__ void __launch_bounds__(128) g2_vlad(const float* __restrict__ x) {
    uint32_t sb = smem_u32(dsm);
    int t = threadIdx.x, w = t >> 5, lane = t & 31;
    int n = blockIdx.y, c0 = blockIdx.x * 64;
    const float* xn = x + (size_t)n * C_ * S_;
    const __half* ahn = g_ah + (size_t)n * K_ * S_;

    float acc[8][4];
#pragma unroll
    for (int j = 0; j < 8; ++j)
#pragma unroll
        for (int q = 0; q < 4; ++q) acc[j][q] = 0.f;
    float4 xr[8];

    // thread owns rows c = it*8 + w*2 + (lane>>4) (it<8), s-quad (lane&15)*4
#define G2_LOADX(ss0)                                                         \
    _Pragma("unroll")                                                         \
    for (int it = 0; it < 8; ++it)                                            \
        xr[it] = *(const float4*)&xn[(size_t)(c0 + it * 8 + w * 2 + (lane >> 4)) * S_ \
                                     + (ss0) + (lane & 15) * 4];
#define G2_CVTX(dst, it) {                                                    \
        float4 v = xr[it];                                                    \
        sts64((dst) + ((it) * 8 + w * 2 + (lane >> 4)) * RS + (lane & 15) * 8,\
              cvt2h(v.x, v.y), cvt2h(v.z, v.w)); }

    G2_LOADX(0);
    stageB(sb + QB(0), ahn, S_, 0, t);
    CP_COMMIT();
#pragma unroll
    for (int it = 0; it < 8; ++it) G2_CVTX(sb + QA(0), it);
    G2_LOADX(64);
    stageB(sb + QB(1), ahn, S_, 64, t);
    CP_COMMIT();
    cp_wait<1>();
    __syncthreads();

    for (int ch = 0; ch < 16; ++ch) {
        int cur = ch & 1, nxt = (ch + 1) & 1;
        bool has_cvt = (ch + 1 < 16);
#pragma unroll
        for (int ks = 0; ks < 4; ++ks) {
            mma_ks1(ks, sb + QA(cur), sb + QB(cur), acc, w, lane);
            if (has_cvt) {
#pragma unroll
                for (int q = 0; q < 2; ++q) G2_CVTX(sb + QA(nxt), ks * 2 + q);
            }
        }
        if (ch + 2 < 16) { G2_LOADX((ch + 2) * 64); }
        __syncthreads();
        if (ch + 2 < 16) {
            stageB(sb + QB(cur), ahn, S_, (ch + 2) * 64, t);
            CP_COMMIT();
            cp_wait<1>();
        } else if (ch + 1 < 16) {
            cp_wait<0>();
        }
        if (ch + 1 < 16) __syncthreads();
    }

    __syncthreads();

    // stage D[64 c][64 k] and write out coalesced over c
    float* Ds = (float*)dsm;
#pragma unroll
    for (int nt = 0; nt < 8; ++nt) {
        int r0 = w * 16 + (lane >> 2);
        int c = nt * 8 + (lane & 3) * 2;
        Ds[r0 * LS_STRIDE + c]           = acc[nt][0];
        Ds[r0 * LS_STRIDE + c + 1]       = acc[nt][1];
        Ds[(r0 + 8) * LS_STRIDE + c]     = acc[nt][2];
        Ds[(r0 + 8) * LS_STRIDE + c + 1] = acc[nt][3];
    }
    __syncthreads();

    int cc = t & 63, kh = (t >> 6) * 32;
#pragma unroll 8
    for (int kk = 0; kk < 32; ++kk) {
        int k = kh + kk;
        g_vlad[(((size_t)n * K_ + k) << 9) + c0 + cc] = Ds[cc * LS_STRIDE + k];
    }
}

// ---------------------------------------------------------------------------
// k4: per-(n,k): val = vlad - asum*centroid; intra-normalize; global norm is
// EXACTLY 8, fold 1/8.
// ---------------------------------------------------------------------------
__global__ void k4_intranorm(const float* __restrict__ centroids,
                             float* __restrict__ out) {
    int nk = blockIdx.x;
    int k = nk & 63;
    int t = threadIdx.x;

    float asum = g_asum[nk];
    float4 vv = ((const float4*)(g_vlad + (size_t)nk * C_))[t];
    float4 cc = ((const float4*)(centroids + (size_t)k * C_))[t];
    float4 val;
    val.x = vv.x - asum * cc.x;
    val.y = vv.y - asum * cc.y;
    val.z = vv.z - asum * cc.z;
    val.w = vv.w - asum * cc.w;
    float ss = val.x * val.x + val.y * val.y + val.z * val.z + val.w * val.w;
#pragma unroll
    for (int o = 16; o; o >>= 1) ss += __shfl_xor_sync(0xffffffffu, ss, o);
    __shared__ float red[4];
    if ((t & 31) == 0) red[t >> 5] = ss;
    __syncthreads();
    float total = red[0] + red[1] + red[2] + red[3];

    float invn = 0.125f / fmaxf(sqrtf(total), 1e-12f);
    val.x *= invn; val.y *= invn; val.z *= invn; val.w *= invn;
    ((float4*)(out + (size_t)nk * C_))[t] = val;
}

// ---------------------------------------------------------------------------
extern "C" void kernel_launch(void* const* d_in, const int* in_sizes, int n_in,
                              void* d_out, int out_size) {
    const float* x    = (const float*)d_in[0];
    const float* w    = (const float*)d_in[1];
    const float* cent = (const float*)d_in[2];
    float* out = (float*)d_out;

    cudaFuncSetAttribute(g1_logits, cudaFuncAttributeMaxDynamicSharedMemorySize, SMEM_G1);
    cudaFuncSetAttribute(g2_vlad,   cudaFuncAttributeMaxDynamicSharedMemorySize, SMEM_G2);

    k0_prep<<<(K_ * C_) / 256, 256>>>(w);
    g1_logits<<<dim3(S_ / 128, N_), 128, SMEM_G1>>>(x);
    g2_vlad<<<dim3(C_ / 64, N_), 128, SMEM_G2>>>(x);
    k4_intranorm<<<N_ * K_, 128>>>(cent, out);
}

// round 14
// speedup vs baseline: 1.0216x; 1.0216x over previous
#include <cuda_runtime.h>
#include <cuda_fp16.h>
#include <math.h>
#include <stdint.h>

#define N_ 64
#define C_ 512
#define S_ 1024
#define K_ 64

// ---- scratch (device globals; allocation-free) ------------------------------
__device__ __half g_wh[K_ * C_];          // w as fp16
__device__ __half g_ah[N_ * K_ * S_];     // a' = softmax*invnorm, fp16
__device__ float g_asum[N_ * K_];
__device__ float g_vlad[N_ * K_ * C_];

// ---- helpers ----------------------------------------------------------------
__device__ __forceinline__ uint32_t smem_u32(const void* p) {
    return (uint32_t)__cvta_generic_to_shared((void*)p);
}
__device__ __forceinline__ void sts64(uint32_t addr, uint32_t v0, uint32_t v1) {
    asm volatile("st.shared.v2.b32 [%0], {%1, %2};" :: "r"(addr), "r"(v0), "r"(v1));
}
__device__ __forceinline__ void sts128(uint32_t addr, uint32_t v0, uint32_t v1,
                                       uint32_t v2, uint32_t v3) {
    asm volatile("st.shared.v4.b32 [%0], {%1, %2, %3, %4};"
                 :: "r"(addr), "r"(v0), "r"(v1), "r"(v2), "r"(v3));
}
__device__ __forceinline__ void cpa16(uint32_t dst, const void* src) {
    asm volatile("cp.async.cg.shared.global [%0], [%1], 16;" :: "r"(dst), "l"(src));
}
#define CP_COMMIT() asm volatile("cp.async.commit_group;" ::: "memory")
template <int N>
__device__ __forceinline__ void cp_wait() {
    asm volatile("cp.async.wait_group %0;" :: "n"(N) : "memory");
}
__device__ __forceinline__ void ldmx4(uint32_t r[4], uint32_t addr) {
    asm volatile("ldmatrix.sync.aligned.m8n8.x4.shared.b16 {%0,%1,%2,%3}, [%4];"
                 : "=r"(r[0]), "=r"(r[1]), "=r"(r[2]), "=r"(r[3]) : "r"(addr));
}
__device__ __forceinline__ void mma16816(float d[4], const uint32_t a[4],
                                         const uint32_t b[2]) {
    asm volatile(
        "mma.sync.aligned.m16n8k16.row.col.f32.f16.f16.f32 "
        "{%0,%1,%2,%3}, {%4,%5,%6,%7}, {%8,%9}, {%0,%1,%2,%3};"
        : "+f"(d[0]), "+f"(d[1]), "+f"(d[2]), "+f"(d[3])
        : "r"(a[0]), "r"(a[1]), "r"(a[2]), "r"(a[3]), "r"(b[0]), "r"(b[1]));
}
// pack two fp32 -> fp16x2 (lo = f0, hi = f1)
__device__ __forceinline__ uint32_t cvt2h(float f0, float f1) {
    uint32_t r;
    asm("cvt.rn.f16x2.f32 %0, %1, %2;" : "=r"(r) : "f"(f1), "f"(f0));
    return r;
}

// smem rows 144B padded (64 fp16 + pad)
#define RS 144
#define LS_STRIDE 66
// A double-buffered (128 rows), B double-buffered (64 rows)
#define OA(b) ((b) * 18432)
#define OB(b) (36864 + (b) * 9216)
#define G1_SSQ 53248
#define SMEM_DYN 55296

extern __shared__ char dsm[];

// ---------------------------------------------------------------------------
// k0: w -> fp16; zero asum.
// ---------------------------------------------------------------------------
__global__ void k0_prep(const float* __restrict__ w) {
    int i = blockIdx.x * 256 + threadIdx.x;
    g_wh[i] = __float2half(w[i]);
    if (i < N_ * K_) g_asum[i] = 0.f;
}

// ---------------------------------------------------------------------------
// B tile stage via cp.async: 64 rows x 64 fp16 from [r*ld + coff]. 4 cp/thread.
// ---------------------------------------------------------------------------
__device__ __forceinline__ void stageB(uint32_t Bd,
                                       const __half* __restrict__ src,
                                       int ld, int coff, int t) {
    int r0 = t >> 3;
    int cc = (t & 7) * 8;
#pragma unroll
    for (int it = 0; it < 4; ++it) {
        int r = it * 16 + r0;
        cpa16(Bd + r * RS + cc * 2, src + (size_t)r * ld + coff + cc);
    }
}

// one ks-slice (k=32 of 64): 6 ldmatrix + 16 HMMA per warp
__device__ __forceinline__ void mma_ks(int ks, uint32_t A, uint32_t B,
                                       float acc[2][8][4], int w, int lane) {
    int arow = lane & 15;
    int asel = (lane >> 4) * 16;
    int brow = (lane & 7) + ((lane >> 4) << 3);
    int bsel = ((lane >> 3) & 1) * 16;
    int kb = ks * 32;
    uint32_t a[2][4];
#pragma unroll
    for (int mt = 0; mt < 2; ++mt)
        ldmx4(a[mt], A + (w * 32 + mt * 16 + arow) * RS + kb + asel);
    uint32_t b[8][2];
#pragma unroll
    for (int p = 0; p < 4; ++p) {
        uint32_t r[4];
        ldmx4(r, B + (p * 16 + brow) * RS + kb + bsel);
        b[2 * p][0] = r[0]; b[2 * p][1] = r[1];
        b[2 * p + 1][0] = r[2]; b[2 * p + 1][1] = r[3];
    }
#pragma unroll
    for (int mt = 0; mt < 2; ++mt)
#pragma unroll
        for (int nt = 0; nt < 8; ++nt)
            mma16816(acc[mt][nt], a[mt], b[nt]);
}

__device__ __forceinline__ void store_frags(float* Ls, float acc[2][8][4],
                                            int w, int lane) {
#pragma unroll
    for (int mt = 0; mt < 2; ++mt)
#pragma unroll
        for (int nt = 0; nt < 8; ++nt) {
            int r0 = w * 32 + mt * 16 + (lane >> 2);
            int c = nt * 8 + (lane & 3) * 2;
            Ls[r0 * LS_STRIDE + c]           = acc[mt][nt][0];
            Ls[r0 * LS_STRIDE + c + 1]       = acc[mt][nt][1];
            Ls[(r0 + 8) * LS_STRIDE + c]     = acc[mt][nt][2];
            Ls[(r0 + 8) * LS_STRIDE + c + 1] = acc[mt][nt][3];
        }
}

// ---------------------------------------------------------------------------
// g1: logits D[s=128,k=64] over C (8 chunks of 64). Single barrier per chunk:
// cp_wait BEFORE the barrier, restage AFTER it.
// ---------------------------------------------------------------------------
__global__ void __launch_bounds__(128) g1_logits(const float* __restrict__ x) {
    uint32_t sb = smem_u32(dsm);
    int t = threadIdx.x, w = t >> 5, lane = t & 31;
    int sl = t & 63, hi = t >> 6;
    int sp = 2 * sl;
    int cb = hi * 32;
    int n = blockIdx.y, s0 = blockIdx.x * 128;
    const float* xn = x + (size_t)n * C_ * S_ + s0;

    float acc[2][8][4];
#pragma unroll
    for (int i = 0; i < 2; ++i)
#pragma unroll
        for (int j = 0; j < 8; ++j)
#pragma unroll
            for (int q = 0; q < 4; ++q) acc[i][j][q] = 0.f;
    float sq0 = 0.f, sq1 = 0.f;
    float2 xr[32];

#define G1_LOADX(cc0)                                                         \
    _Pragma("unroll")                                                         \
    for (int j = 0; j < 32; ++j)                                              \
        xr[j] = *(const float2*)&xn[(size_t)((cc0) + cb + j) * S_ + sp];

#define G1_CVTG(dst, g) {                                                     \
        uint32_t u0[4], u1[4];                                                \
        _Pragma("unroll")                                                     \
        for (int q = 0; q < 4; ++q) {                                         \
            int cp = (g) * 4 + q;                                             \
            float2 va = xr[2 * cp], vb = xr[2 * cp + 1];                      \
            sq0 += va.x * va.x + vb.x * vb.x;                                 \
            sq1 += va.y * va.y + vb.y * vb.y;                                 \
            u0[q] = cvt2h(va.x, vb.x);                                        \
            u1[q] = cvt2h(va.y, vb.y);                                        \
        }                                                                     \
        sts128((dst) + sp * RS + (cb + (g) * 8) * 2,                          \
               u0[0], u0[1], u0[2], u0[3]);                                   \
        sts128((dst) + (sp + 1) * RS + (cb + (g) * 8) * 2,                    \
               u1[0], u1[1], u1[2], u1[3]); }

    G1_LOADX(0);
    stageB(sb + OB(0), g_wh, C_, 0, t);
    CP_COMMIT();
#pragma unroll
    for (int g = 0; g < 4; ++g) G1_CVTG(sb + OA(0), g);
    G1_LOADX(64);
    stageB(sb + OB(1), g_wh, C_, 64, t);
    CP_COMMIT();
    cp_wait<1>();
    __syncthreads();

    for (int ch = 0; ch < 8; ++ch) {
        int cur = ch & 1, nxt = cur ^ 1;
        bool has_cvt = (ch + 1 < 8);
#pragma unroll
        for (int ks = 0; ks < 4; ++ks) {
            mma_ks(ks, sb + OA(cur), sb + OB(cur), acc, w, lane);
            if (has_cvt) G1_CVTG(sb + OA(nxt), ks);
        }
        if (ch + 2 < 8) { G1_LOADX((ch + 2) * 64); }
        if (ch + 1 < 8) {
            cp_wait<0>();        // B[ch+1] (committed last iter) complete
            __syncthreads();     // publish A[nxt]+B[nxt]; free A[cur]/B[cur]
        }
        if (ch + 2 < 8) {
            stageB(sb + OB(cur), g_wh, C_, (ch + 2) * 64, t);
            CP_COMMIT();
        }
    }

    __syncthreads();  // last chunk's tile reads done before epilogue staging

    float* Ls = (float*)dsm;
    float* ssq = (float*)(dsm + G1_SSQ);
    ssq[hi * 128 + sp]     = sq0;
    ssq[hi * 128 + sp + 1] = sq1;
    store_frags(Ls, acc, w, lane);
    __syncthreads();

    float sumsq = ssq[t] + ssq[128 + t];
    float inv = 1.f / fmaxf(sqrtf(sumsq), 1e-12f);
    float m = -1e30f;
#pragma unroll
    for (int k = 0; k < K_; ++k) m = fmaxf(m, Ls[t * LS_STRIDE + k] * inv);
    float sum = 0.f;
#pragma unroll
    for (int k = 0; k < K_; ++k) {
        float e = expf(Ls[t * LS_STRIDE + k] * inv - m);
        Ls[t * LS_STRIDE + k] = e;
        sum += e;
    }
    float rs = 1.f / sum;
#pragma unroll
    for (int k = 0; k < K_; ++k) {
        float a = Ls[t * LS_STRIDE + k] * rs;
        Ls[t * LS_STRIDE + k] = a;
        g_ah[(((size_t)n * K_ + k) << 10) + s0 + t] = __float2half(a * inv);
    }
    __syncthreads();
    if (t < K_) {
        float s = 0.f;
#pragma unroll
        for (int si = 0; si < 128; ++si) s += Ls[si * LS_STRIDE + t];
        atomicAdd(&g_asum[n * K_ + t], s);
    }
}

// ---------------------------------------------------------------------------
// g2: vlad D[c=128,k=64] over S (16 chunks of 64). R11 tile config (proven),
// single barrier per chunk.
// ---------------------------------------------------------------------------
__global__ void __launch_bounds__(128) g2_vlad(const float* __restrict__ x) {
    uint32_t sb = smem_u32(dsm);
    int t = threadIdx.x, w = t >> 5, lane = t & 31;
    int n = blockIdx.y, c0 = blockIdx.x * 128;
    const float* xn = x + (size_t)n * C_ * S_;
    const __half* ahn = g_ah + (size_t)n * K_ * S_;

    float acc[2][8][4];
#pragma unroll
    for (int i = 0; i < 2; ++i)
#pragma unroll
        for (int j = 0; j < 8; ++j)
#pragma unroll
            for (int q = 0; q < 4; ++q) acc[i][j][q] = 0.f;
    float4 xr[16];

    // thread owns rows c = it*8 + w*2 + (lane>>4), s-quad (lane&15)*4
#define G2_LOADX(ss0)                                                         \
    _Pragma("unroll")                                                         \
    for (int it = 0; it < 16; ++it)                                           \
        xr[it] = *(const float4*)&xn[(size_t)(c0 + it * 8 + w * 2 + (lane >> 4)) * S_ \
                                     + (ss0) + (lane & 15) * 4];
#define G2_CVTX(dst, it) {                                                    \
        float4 v = xr[it];                                                    \
        sts64((dst) + ((it) * 8 + w * 2 + (lane >> 4)) * RS + (lane & 15) * 8,\
              cvt2h(v.x, v.y), cvt2h(v.z, v.w)); }

    G2_LOADX(0);
    stageB(sb + OB(0), ahn, S_, 0, t);
    CP_COMMIT();
#pragma unroll
    for (int it = 0; it < 16; ++it) G2_CVTX(sb + OA(0), it);
    G2_LOADX(64);
    stageB(sb + OB(1), ahn, S_, 64, t);
    CP_COMMIT();
    cp_wait<1>();
    __syncthreads();

    for (int ch = 0; ch < 16; ++ch) {
        int cur = ch & 1, nxt = cur ^ 1;
        bool has_cvt = (ch + 1 < 16);
#pragma unroll
        for (int ks = 0; ks < 4; ++ks) {
            mma_ks(ks, sb + OA(cur), sb + OB(cur), acc, w, lane);
            if (has_cvt) {
#pragma unroll
                for (int q = 0; q < 4; ++q) G2_CVTX(sb + OA(nxt), ks * 4 + q);
            }
        }
        if (ch + 2 < 16) { G2_LOADX((ch + 2) * 64); }
        if (ch + 1 < 16) {
            cp_wait<0>();
            __syncthreads();
        }
        if (ch + 2 < 16) {
            stageB(sb + OB(cur), ahn, S_, (ch + 2) * 64, t);
            CP_COMMIT();
        }
    }

    __syncthreads();  // last chunk's tile reads done before epilogue staging

    float* Ds = (float*)dsm;
    store_frags(Ds, acc, w, lane);
    __syncthreads();

#pragma unroll 4
    for (int k = 0; k < K_; ++k)
        g_vlad[(((size_t)n * K_ + k) << 9) + c0 + t] = Ds[t * LS_STRIDE + k];
}

// ---------------------------------------------------------------------------
// k4: per-(n,k): val = vlad - asum*centroid; intra-normalize; global norm is
// EXACTLY 8, fold 1/8.
// ---------------------------------------------------------------------------
__global__ void k4_intranorm(const float* __restrict__ centroids,
                             float* __restrict__ out) {
    int nk = blockIdx.x;
    int k = nk & 63;
    int t = threadIdx.x;

    float asum = g_asum[nk];
    float4 vv = ((const float4*)(g_vlad + (size_t)nk * C_))[t];
    float4 cc = ((const float4*)(centroids + (size_t)k * C_))[t];
    float4 val;
    val.x = vv.x - asum * cc.x;
    val.y = vv.y - asum * cc.y;
    val.z = vv.z - asum * cc.z;
    val.w = vv.w - asum * cc.w;
    float ss = val.x * val.x + val.y * val.y + val.z * val.z + val.w * val.w;
#pragma unroll
    for (int o = 16; o; o >>= 1) ss += __shfl_xor_sync(0xffffffffu, ss, o);
    __shared__ float red[4];
    if ((t & 31) == 0) red[t >> 5] = ss;
    __syncthreads();
    float total = red[0] + red[1] + red[2] + red[3];

    float invn = 0.125f / fmaxf(sqrtf(total), 1e-12f);
    val.x *= invn; val.y *= invn; val.z *= invn; val.w *= invn;
    ((float4*)(out + (size_t)nk * C_))[t] = val;
}

// ---------------------------------------------------------------------------
extern "C" void kernel_launch(void* const* d_in, const int* in_sizes, int n_in,
                              void* d_out, int out_size) {
    const float* x    = (const float*)d_in[0];
    const float* w    = (const float*)d_in[1];
    const float* cent = (const float*)d_in[2];
    float* out = (float*)d_out;

    cudaFuncSetAttribute(g1_logits, cudaFuncAttributeMaxDynamicSharedMemorySize, SMEM_DYN);
    cudaFuncSetAttribute(g2_vlad,   cudaFuncAttributeMaxDynamicSharedMemorySize, SMEM_DYN);

    k0_prep<<<(K_ * C_) / 256, 256>>>(w);
    g1_logits<<<dim3(S_ / 128, N_), 128, SMEM_DYN>>>(x);
    g2_vlad<<<dim3(C_ / 128, N_), 128, SMEM_DYN>>>(x);
    k4_intranorm<<<N_ * K_, 128>>>(cent, out);
}